// round 1
// baseline (speedup 1.0000x reference)
#include <cuda_runtime.h>
#include <math.h>

#define BB   8
#define CIN  64
#define COUT 64
#define CG   16
#define HH   128
#define WW   128
#define TILE 16
#define CCHUNK 8

// Per-pixel adaptive kernel scratch: [b][p][h][w], 8*9*128*128 floats = 4.7 MB
__device__ float g_kern[BB * 9 * HH * WW];

// ---------------------------------------------------------------------------
// Kernel 1: Gaussian guidance kernel precompute.
// kern[b,p,h,w] = exp(-0.5 * sum_g (guide_pad[b,g,h+dh,w+dw] - guide[b,g,h,w])^2)
// Zero-padded guide: out-of-bounds tap contributes sum_g guide_center^2.
// ---------------------------------------------------------------------------
__global__ void kern_precompute(const float* __restrict__ guide) {
    int idx = blockIdx.x * blockDim.x + threadIdx.x;
    if (idx >= BB * HH * WW) return;
    int w = idx % WW;
    int h = (idx / WW) % HH;
    int b = idx / (HH * WW);

    const float* gb = guide + (size_t)b * CG * HH * WW;
    float gc[CG];
#pragma unroll
    for (int c = 0; c < CG; c++) gc[c] = gb[c * HH * WW + h * WW + w];

#pragma unroll
    for (int p = 0; p < 9; p++) {
        int hh = h + p / 3 - 1;
        int ww = w + p % 3 - 1;
        float ss = 0.f;
        if (hh >= 0 && hh < HH && ww >= 0 && ww < WW) {
#pragma unroll
            for (int c = 0; c < CG; c++) {
                float d = gb[c * HH * WW + hh * WW + ww] - gc[c];
                ss = fmaf(d, d, ss);
            }
        } else {
#pragma unroll
            for (int c = 0; c < CG; c++) ss = fmaf(gc[c], gc[c], ss);
        }
        g_kern[((b * 9 + p) * HH + h) * WW + w] = expf(-0.5f * ss);
    }
}

// ---------------------------------------------------------------------------
// Kernel 2: main PAC conv.
// Block = 16x16 spatial tile of one batch image; 256 threads, each thread owns
// one pixel and all 64 Cout accumulators. Cin processed in chunks of 8.
// Weights staged in smem as [c][p][o] so the whole block broadcast-reads the
// same float4 (conflict-free), keeping the loop FMA-bound rather than LDS-bound.
// ---------------------------------------------------------------------------
__global__ __launch_bounds__(256) void pac_conv(
    const float* __restrict__ x,
    const float* __restrict__ weight,   // [o][c][3][3]
    const float* __restrict__ bias,
    float* __restrict__ out) {

    __shared__ __align__(16) float ws[CCHUNK * 9 * COUT];        // [c][p][o]
    __shared__ float xs[CCHUNK][TILE + 2][TILE + 2];

    const int tid = threadIdx.x;
    const int tx = tid % TILE;
    const int ty = tid / TILE;
    const int b  = blockIdx.z;
    const int h0 = blockIdx.y * TILE;
    const int w0 = blockIdx.x * TILE;
    const int h  = h0 + ty;
    const int w  = w0 + tx;

    // per-pixel adaptive kernel taps (coalesced: one plane per tap)
    float kv[9];
#pragma unroll
    for (int p = 0; p < 9; p++)
        kv[p] = g_kern[((b * 9 + p) * HH + h) * WW + w];

    float acc[COUT];
#pragma unroll
    for (int o = 0; o < COUT; o++) acc[o] = 0.f;

    for (int cc = 0; cc < CIN; cc += CCHUNK) {
        __syncthreads();
        // stage x halo tile: CCHUNK x 18 x 18
        for (int i = tid; i < CCHUNK * 18 * 18; i += 256) {
            int c  = i / 324;
            int r  = i % 324;
            int yy = r / 18;
            int xx = r % 18;
            int gh = h0 + yy - 1;
            int gw = w0 + xx - 1;
            float v = 0.f;
            if (gh >= 0 && gh < HH && gw >= 0 && gw < WW)
                v = x[(((size_t)b * CIN + cc + c) * HH + gh) * WW + gw];
            xs[c][yy][xx] = v;
        }
        // stage weights transposed to [c][p][o]
        for (int i = tid; i < CCHUNK * 9 * COUT; i += 256) {
            int o = i % COUT;
            int p = (i / COUT) % 9;
            int c = i / (9 * COUT);
            ws[i] = weight[((size_t)o * CIN + cc + c) * 9 + p];
        }
        __syncthreads();

#pragma unroll 2
        for (int c = 0; c < CCHUNK; c++) {
            float xk[9];
#pragma unroll
            for (int p = 0; p < 9; p++)
                xk[p] = xs[c][ty + p / 3][tx + p % 3] * kv[p];

            const float4* w4 = reinterpret_cast<const float4*>(&ws[c * 9 * COUT]);
#pragma unroll
            for (int p = 0; p < 9; p++) {
#pragma unroll
                for (int o4 = 0; o4 < COUT / 4; o4++) {
                    float4 wv = w4[p * (COUT / 4) + o4];
                    acc[o4 * 4 + 0] = fmaf(xk[p], wv.x, acc[o4 * 4 + 0]);
                    acc[o4 * 4 + 1] = fmaf(xk[p], wv.y, acc[o4 * 4 + 1]);
                    acc[o4 * 4 + 2] = fmaf(xk[p], wv.z, acc[o4 * 4 + 2]);
                    acc[o4 * 4 + 3] = fmaf(xk[p], wv.w, acc[o4 * 4 + 3]);
                }
            }
        }
    }

#pragma unroll
    for (int o = 0; o < COUT; o++) {
        float v = acc[o] + __ldg(&bias[o]);
        out[(((size_t)b * COUT + o) * HH + h) * WW + w] = fmaxf(v, 0.f);
    }
}

// ---------------------------------------------------------------------------
extern "C" void kernel_launch(void* const* d_in, const int* in_sizes, int n_in,
                              void* d_out, int out_size) {
    const float* x      = (const float*)d_in[0];   // (8,64,128,128)
    const float* guide  = (const float*)d_in[1];   // (8,16,128,128)
    const float* weight = (const float*)d_in[2];   // (64,64,3,3)
    const float* bias   = (const float*)d_in[3];   // (64,)
    float* out = (float*)d_out;                    // (8,64,128,128)

    (void)in_sizes; (void)n_in; (void)out_size;

    int npix = BB * HH * WW;
    kern_precompute<<<(npix + 255) / 256, 256>>>(guide);

    dim3 grid(WW / TILE, HH / TILE, BB);
    pac_conv<<<grid, 256>>>(x, weight, bias, out);
}

// round 2
// speedup vs baseline: 1.0349x; 1.0349x over previous
#include <cuda_runtime.h>
#include <math.h>

#define BB   8
#define CIN  64
#define COUT 64
#define CG   16
#define HH   128
#define WW   128
#define TILE 16
#define CCHUNK 8

// Per-pixel adaptive kernel scratch: [b][p][h][w]
__device__ float g_kern[BB * 9 * HH * WW];

// ---------------------------------------------------------------------------
// packed fp32x2 helpers (Blackwell f32x2 pipe)
// ---------------------------------------------------------------------------
__device__ __forceinline__ unsigned long long pack2(float lo, float hi) {
    unsigned long long r;
    asm("mov.b64 %0, {%1, %2};" : "=l"(r) : "f"(lo), "f"(hi));
    return r;
}
__device__ __forceinline__ void unpack2(unsigned long long v, float& lo, float& hi) {
    asm("mov.b64 {%0, %1}, %2;" : "=f"(lo), "=f"(hi) : "l"(v));
}
__device__ __forceinline__ unsigned long long ffma2(unsigned long long a,
                                                    unsigned long long b,
                                                    unsigned long long c) {
    unsigned long long d;
    asm("fma.rn.f32x2 %0, %1, %2, %3;" : "=l"(d) : "l"(a), "l"(b), "l"(c));
    return d;
}

// ---------------------------------------------------------------------------
// Kernel 1: Gaussian guidance kernel precompute (unchanged, correct & cheap)
// ---------------------------------------------------------------------------
__global__ void kern_precompute(const float* __restrict__ guide) {
    int idx = blockIdx.x * blockDim.x + threadIdx.x;
    if (idx >= BB * HH * WW) return;
    int w = idx % WW;
    int h = (idx / WW) % HH;
    int b = idx / (HH * WW);

    const float* gb = guide + (size_t)b * CG * HH * WW;
    float gc[CG];
#pragma unroll
    for (int c = 0; c < CG; c++) gc[c] = gb[c * HH * WW + h * WW + w];

#pragma unroll
    for (int p = 0; p < 9; p++) {
        int hh = h + p / 3 - 1;
        int ww = w + p % 3 - 1;
        float ss = 0.f;
        if (hh >= 0 && hh < HH && ww >= 0 && ww < WW) {
#pragma unroll
            for (int c = 0; c < CG; c++) {
                float d = gb[c * HH * WW + hh * WW + ww] - gc[c];
                ss = fmaf(d, d, ss);
            }
        } else {
#pragma unroll
            for (int c = 0; c < CG; c++) ss = fmaf(gc[c], gc[c], ss);
        }
        g_kern[((b * 9 + p) * HH + h) * WW + w] = expf(-0.5f * ss);
    }
}

// ---------------------------------------------------------------------------
// Kernel 2: register-blocked PAC conv with packed f32x2 FMAs.
// Block: 16x16 pixels x 64 Cout, 256 threads.
// Thread: q = tid&3 -> cout group (16 couts), g = tid>>2 -> 4 pixels in a row.
// Each thread: 4 pixels x 16 couts = 32 packed accumulators.
// ---------------------------------------------------------------------------
__global__ __launch_bounds__(256) void pac_conv(
    const float* __restrict__ x,
    const float* __restrict__ weight,   // [o][c][3][3]
    const float* __restrict__ bias,
    float* __restrict__ out) {

    __shared__ __align__(16) float ws[CCHUNK * 9 * COUT];   // [c][p][o]
    __shared__ __align__(16) float xs[CCHUNK][18][20];      // padded row stride 20

    const int tid = threadIdx.x;
    const int q   = tid & 3;          // cout group: couts q*16 .. q*16+15
    const int g   = tid >> 2;         // pixel group 0..63
    const int ty  = g >> 2;           // row within tile 0..15
    const int txg = g & 3;            // 4-pixel column group 0..3

    const int b  = blockIdx.z;
    const int h0 = blockIdx.y * TILE;
    const int w0 = blockIdx.x * TILE;
    const int h     = h0 + ty;
    const int wbase = w0 + txg * 4;

    // per-pixel adaptive kernel taps: 9 taps x 4 pixels (float4 over pixels)
    float4 kv4[9];
#pragma unroll
    for (int p = 0; p < 9; p++)
        kv4[p] = *reinterpret_cast<const float4*>(
            &g_kern[((b * 9 + p) * HH + h) * WW + wbase]);

    unsigned long long acc2[4][8];
#pragma unroll
    for (int i = 0; i < 4; i++)
#pragma unroll
        for (int j = 0; j < 8; j++) acc2[i][j] = 0ULL;

    for (int cc = 0; cc < CIN; cc += CCHUNK) {
        __syncthreads();
        // stage x halo tile: CCHUNK x 18 x 18 (row stride 20)
        for (int i = tid; i < CCHUNK * 18 * 18; i += 256) {
            int c  = i / 324;
            int r  = i % 324;
            int yy = r / 18;
            int xx = r % 18;
            int gh = h0 + yy - 1;
            int gw = w0 + xx - 1;
            float v = 0.f;
            if (gh >= 0 && gh < HH && gw >= 0 && gw < WW)
                v = x[(((size_t)b * CIN + cc + c) * HH + gh) * WW + gw];
            xs[c][yy][xx] = v;
        }
        // stage weights transposed to [c][p][o]
        for (int i = tid; i < CCHUNK * 9 * COUT; i += 256) {
            int o = i % COUT;
            int p = (i / COUT) % 9;
            int c = i / (9 * COUT);
            ws[i] = weight[((size_t)o * CIN + cc + c) * 9 + p];
        }
        __syncthreads();

#pragma unroll
        for (int c = 0; c < CCHUNK; c++) {
#pragma unroll
            for (int dh = 0; dh < 3; dh++) {
                // 6 consecutive x values cover 3 horizontal taps for 4 pixels
                const float* r = &xs[c][ty + dh][txg * 4];
                float4 ra = *reinterpret_cast<const float4*>(r);
                float2 rb = *reinterpret_cast<const float2*>(r + 4);
                float xr[6] = {ra.x, ra.y, ra.z, ra.w, rb.x, rb.y};
#pragma unroll
                for (int dw = 0; dw < 3; dw++) {
                    const int p = dh * 3 + dw;
                    const float4 kk = kv4[p];
                    float xk0 = xr[0 + dw] * kk.x;
                    float xk1 = xr[1 + dw] * kk.y;
                    float xk2 = xr[2 + dw] * kk.z;
                    float xk3 = xr[3 + dw] * kk.w;

                    const float4* wp = reinterpret_cast<const float4*>(
                        &ws[(c * 9 + p) * COUT + q * 16]);
                    float4 w0v = wp[0], w1v = wp[1], w2v = wp[2], w3v = wp[3];
                    unsigned long long wb[8];
                    wb[0] = pack2(w0v.x, w0v.y); wb[1] = pack2(w0v.z, w0v.w);
                    wb[2] = pack2(w1v.x, w1v.y); wb[3] = pack2(w1v.z, w1v.w);
                    wb[4] = pack2(w2v.x, w2v.y); wb[5] = pack2(w2v.z, w2v.w);
                    wb[6] = pack2(w3v.x, w3v.y); wb[7] = pack2(w3v.z, w3v.w);

                    unsigned long long a0 = pack2(xk0, xk0);
                    unsigned long long a1 = pack2(xk1, xk1);
                    unsigned long long a2 = pack2(xk2, xk2);
                    unsigned long long a3 = pack2(xk3, xk3);
#pragma unroll
                    for (int j = 0; j < 8; j++) {
                        acc2[0][j] = ffma2(a0, wb[j], acc2[0][j]);
                        acc2[1][j] = ffma2(a1, wb[j], acc2[1][j]);
                        acc2[2][j] = ffma2(a2, wb[j], acc2[2][j]);
                        acc2[3][j] = ffma2(a3, wb[j], acc2[3][j]);
                    }
                }
            }
        }
    }

    // epilogue: bias + relu, float4 store over the 4-pixel dimension
#pragma unroll
    for (int j = 0; j < 8; j++) {
        float lo[4], hi[4];
#pragma unroll
        for (int i = 0; i < 4; i++) unpack2(acc2[i][j], lo[i], hi[i]);

        int o0 = q * 16 + 2 * j;
        float b0 = __ldg(&bias[o0]);
        float b1 = __ldg(&bias[o0 + 1]);

        float4 v0, v1;
        v0.x = fmaxf(lo[0] + b0, 0.f); v0.y = fmaxf(lo[1] + b0, 0.f);
        v0.z = fmaxf(lo[2] + b0, 0.f); v0.w = fmaxf(lo[3] + b0, 0.f);
        v1.x = fmaxf(hi[0] + b1, 0.f); v1.y = fmaxf(hi[1] + b1, 0.f);
        v1.z = fmaxf(hi[2] + b1, 0.f); v1.w = fmaxf(hi[3] + b1, 0.f);

        *reinterpret_cast<float4*>(
            &out[(((size_t)b * COUT + o0) * HH + h) * WW + wbase]) = v0;
        *reinterpret_cast<float4*>(
            &out[(((size_t)b * COUT + o0 + 1) * HH + h) * WW + wbase]) = v1;
    }
}

// ---------------------------------------------------------------------------
extern "C" void kernel_launch(void* const* d_in, const int* in_sizes, int n_in,
                              void* d_out, int out_size) {
    const float* x      = (const float*)d_in[0];   // (8,64,128,128)
    const float* guide  = (const float*)d_in[1];   // (8,16,128,128)
    const float* weight = (const float*)d_in[2];   // (64,64,3,3)
    const float* bias   = (const float*)d_in[3];   // (64,)
    float* out = (float*)d_out;                    // (8,64,128,128)

    (void)in_sizes; (void)n_in; (void)out_size;

    int npix = BB * HH * WW;
    kern_precompute<<<(npix + 255) / 256, 256>>>(guide);

    dim3 grid(WW / TILE, HH / TILE, BB);
    pac_conv<<<grid, 256>>>(x, weight, bias, out);
}

// round 4
// speedup vs baseline: 3.2380x; 3.1288x over previous
#include <cuda_runtime.h>
#include <cuda_bf16.h>
#include <math.h>
#include <stdint.h>

#define BB   8
#define CIN  64
#define COUT 64
#define CG   16
#define HH   128
#define WW   128

// ---------------------------------------------------------------------------
// device scratch
// ---------------------------------------------------------------------------
__device__ float    g_kern[BB * 9 * HH * WW];
// weight fragments: [p][v(hi/lo)][nt(8)][kt(4)][lane(32)][r(2)] packed bf16x2
__device__ uint32_t g_wfrag[9 * 2 * 2048];

// smem layout (bytes)
#define SOFF_BIAS 0
#define SOFF_KERN 256
#define SOFF_B    4864            // 2 x 16384 double buffer
#define SOFF_XH   37632           // [dh(3)][col(130)][c] stride 72 elems bf16
#define SOFF_XL   93792
#define SMEM_TOTAL 149952

__device__ __forceinline__ uint32_t smem_u32(const void* p) {
    uint32_t a;
    asm("{ .reg .u64 t; cvta.to.shared.u64 t, %1; cvt.u32.u64 %0, t; }"
        : "=r"(a) : "l"(p));
    return a;
}

__device__ __forceinline__ void ldm_x4(uint32_t r[4], uint32_t addr) {
    asm volatile("ldmatrix.sync.aligned.m8n8.x4.shared.b16 {%0,%1,%2,%3}, [%4];"
                 : "=r"(r[0]), "=r"(r[1]), "=r"(r[2]), "=r"(r[3]) : "r"(addr));
}

#define MMA_BF16(d, a, b0, b1)                                                 \
    asm volatile("mma.sync.aligned.m16n8k16.row.col.f32.bf16.bf16.f32 "        \
                 "{%0,%1,%2,%3}, {%4,%5,%6,%7}, {%8,%9}, {%0,%1,%2,%3};"       \
                 : "+f"((d)[0]), "+f"((d)[1]), "+f"((d)[2]), "+f"((d)[3])      \
                 : "r"((a)[0]), "r"((a)[1]), "r"((a)[2]), "r"((a)[3]),         \
                   "r"(b0), "r"(b1))

// ---------------------------------------------------------------------------
// Kernel 1: Gaussian guidance kernel precompute
// ---------------------------------------------------------------------------
__global__ void kern_precompute(const float* __restrict__ guide) {
    int idx = blockIdx.x * blockDim.x + threadIdx.x;
    if (idx >= BB * HH * WW) return;
    int w = idx % WW;
    int h = (idx / WW) % HH;
    int b = idx / (HH * WW);

    const float* gb = guide + (size_t)b * CG * HH * WW;
    float gc[CG];
#pragma unroll
    for (int c = 0; c < CG; c++) gc[c] = gb[c * HH * WW + h * WW + w];

#pragma unroll
    for (int p = 0; p < 9; p++) {
        int hh = h + p / 3 - 1;
        int ww = w + p % 3 - 1;
        float ss = 0.f;
        if (hh >= 0 && hh < HH && ww >= 0 && ww < WW) {
#pragma unroll
            for (int c = 0; c < CG; c++) {
                float d = gb[c * HH * WW + hh * WW + ww] - gc[c];
                ss = fmaf(d, d, ss);
            }
        } else {
#pragma unroll
            for (int c = 0; c < CG; c++) ss = fmaf(gc[c], gc[c], ss);
        }
        g_kern[((b * 9 + p) * HH + h) * WW + w] = expf(-0.5f * ss);
    }
}

// ---------------------------------------------------------------------------
// Kernel 1b: shuffle weights into mma B-fragment order, bf16 hi/lo split.
// word i = [p][v][nt][kt][lane][r]; value = {w[o][c], w[o][c+1]} bf16x2
// o = nt*8 + lane/4, c = kt*16 + (lane%4)*2 + r*8
// ---------------------------------------------------------------------------
__global__ void weight_split(const float* __restrict__ weight) {
    int i = blockIdx.x * 256 + threadIdx.x;
    if (i >= 9 * 2 * 2048) return;
    int p    = i >> 12;
    int v    = (i >> 11) & 1;
    int nt   = (i >> 8) & 7;
    int kt   = (i >> 6) & 3;
    int lane = (i >> 1) & 31;
    int r    = i & 1;
    int o = nt * 8 + (lane >> 2);
    int c = kt * 16 + (lane & 3) * 2 + r * 8;
    float v0 = weight[((size_t)o * CIN + c) * 9 + p];
    float v1 = weight[((size_t)o * CIN + c + 1) * 9 + p];
    __nv_bfloat16 h0 = __float2bfloat16_rn(v0);
    __nv_bfloat16 h1 = __float2bfloat16_rn(v1);
    unsigned short u0, u1;
    if (v == 0) {
        u0 = __bfloat16_as_ushort(h0);
        u1 = __bfloat16_as_ushort(h1);
    } else {
        u0 = __bfloat16_as_ushort(__float2bfloat16_rn(v0 - __bfloat162float(h0)));
        u1 = __bfloat16_as_ushort(__float2bfloat16_rn(v1 - __bfloat162float(h1)));
    }
    g_wfrag[i] = ((uint32_t)u1 << 16) | u0;
}

// ---------------------------------------------------------------------------
// Main: one CTA = one output row (128 pixels) of one image.
// out[pix, o] = sum_p kv[p][pix] * (Xshift_p[pix, c] @ W_p[c, o]),
// mma.sync m16n8k16 bf16, 3-chain bf16x3 precision split, fp32 accum.
// 512 threads = 16 warps: warpM = wid&3 (32 pix), warpN = wid>>2 (16 couts).
// ---------------------------------------------------------------------------
__global__ __launch_bounds__(512, 1)
void pac_mma(const float* __restrict__ x,
             const float* __restrict__ bias,
             float* __restrict__ out) {
    extern __shared__ __align__(16) char smem[];
    const uint32_t sb = smem_u32(smem);
    float* bias_s = (float*)(smem + SOFF_BIAS);
    float* kern_s = (float*)(smem + SOFF_KERN);
    __nv_bfloat16* xh_s = (__nv_bfloat16*)(smem + SOFF_XH);
    __nv_bfloat16* xl_s = (__nv_bfloat16*)(smem + SOFF_XL);

    const int tid   = threadIdx.x;
    const int lane  = tid & 31;
    const int wid   = tid >> 5;
    const int warpM = wid & 3;
    const int warpN = wid >> 2;
    const int h = blockIdx.x;
    const int b = blockIdx.y;

    // stage x halo as bf16 hi/lo, pixel-major: [dh][col][c], stride 72
    for (int i = tid; i < 3 * 130 * CIN; i += 512) {
        int col = i % 130;
        int c   = (i / 130) & 63;
        int dh  = i / (130 * 64);
        int gr = h - 1 + dh, gc = col - 1;
        float v = 0.f;
        if (gr >= 0 && gr < HH && gc >= 0 && gc < WW)
            v = x[(((size_t)b * CIN + c) * HH + gr) * WW + gc];
        __nv_bfloat16 hi = __float2bfloat16_rn(v);
        int off = (dh * 130 + col) * 72 + c;
        xh_s[off] = hi;
        xl_s[off] = __float2bfloat16_rn(v - __bfloat162float(hi));
    }
    // stage per-pixel gaussian taps + bias
    for (int i = tid; i < 9 * 128; i += 512)
        kern_s[i] = g_kern[((size_t)(b * 9 + (i >> 7)) * HH + h) * WW + (i & 127)];
    if (tid < COUT) bias_s[tid] = bias[tid];

    // prefetch B for tap 0 (16KB: hi 8KB + lo 8KB, fragment order)
    {
        const char* src = (const char*)g_wfrag;
#pragma unroll
        for (int j = 0; j < 2; j++) {
            uint32_t dst = sb + SOFF_B + (uint32_t)((j * 512 + tid) * 16);
            asm volatile("cp.async.ca.shared.global [%0], [%1], 16;"
                         :: "r"(dst), "l"(src + (j * 512 + tid) * 16) : "memory");
        }
        asm volatile("cp.async.commit_group;" ::: "memory");
    }

    float acc[2][2][4];
#pragma unroll
    for (int i = 0; i < 2; i++)
#pragma unroll
        for (int j = 0; j < 2; j++)
#pragma unroll
            for (int k = 0; k < 4; k++) acc[i][j][k] = 0.f;

    // per-thread ldmatrix address part: row = pixel (lane&15), kcol quad
    const uint32_t a_thread =
        (uint32_t)((((lane & 15) * 72) + ((lane >> 4) << 3)) * 2) + warpM * 4608u;

#pragma unroll 1
    for (int p = 0; p < 9; p++) {
        const int dh = p / 3, dw = p - dh * 3;
        const int buf = p & 1;

        __syncthreads();   // previous tap's B reads done
        if (p + 1 < 9) {
            const char* src = (const char*)g_wfrag + (p + 1) * 16384;
            uint32_t dstb = sb + SOFF_B + (uint32_t)(((p + 1) & 1) * 16384);
#pragma unroll
            for (int j = 0; j < 2; j++) {
                asm volatile("cp.async.ca.shared.global [%0], [%1], 16;"
                             :: "r"(dstb + (uint32_t)((j * 512 + tid) * 16)),
                                "l"(src + (j * 512 + tid) * 16) : "memory");
            }
            asm volatile("cp.async.commit_group;" ::: "memory");
            asm volatile("cp.async.wait_group 1;" ::: "memory");
        } else {
            asm volatile("cp.async.wait_group 0;" ::: "memory");
        }
        __syncthreads();   // tap p's B visible

        float T[2][2][4];
#pragma unroll
        for (int i = 0; i < 2; i++)
#pragma unroll
            for (int j = 0; j < 2; j++)
#pragma unroll
                for (int k = 0; k < 4; k++) T[i][j][k] = 0.f;

        const uint32_t a_tap = a_thread + (uint32_t)((dh * 130 + dw) * 144);
        const char* bbase = smem + SOFF_B + buf * 16384;

#pragma unroll
        for (int kt = 0; kt < 4; kt++) {
            uint32_t Ah[2][4], Al[2][4];
#pragma unroll
            for (int mt = 0; mt < 2; mt++) {
                uint32_t ad = sb + SOFF_XH + a_tap + (uint32_t)(kt * 32 + mt * 2304);
                ldm_x4(Ah[mt], ad);
                ldm_x4(Al[mt], ad + (SOFF_XL - SOFF_XH));
            }
#pragma unroll
            for (int nt = 0; nt < 2; nt++) {
                const int ntg = warpN * 2 + nt;
                const uint2* bp = (const uint2*)(bbase +
                    (size_t)((ntg * 256 + kt * 64) * 4) + lane * 8);
                uint2 bh = bp[0];
                uint2 bl = bp[1024];   // lo block is +8192 bytes
#pragma unroll
                for (int mt = 0; mt < 2; mt++) {
                    MMA_BF16(T[mt][nt], Ah[mt], bh.x, bh.y);
                    MMA_BF16(T[mt][nt], Al[mt], bh.x, bh.y);
                    MMA_BF16(T[mt][nt], Ah[mt], bl.x, bl.y);
                }
            }
        }

        // scale by per-pixel gaussian and accumulate
#pragma unroll
        for (int mt = 0; mt < 2; mt++) {
            int pix = warpM * 32 + mt * 16 + (lane >> 2);
            float kv0 = kern_s[p * 128 + pix];
            float kv1 = kern_s[p * 128 + pix + 8];
#pragma unroll
            for (int nt = 0; nt < 2; nt++) {
                acc[mt][nt][0] = fmaf(kv0, T[mt][nt][0], acc[mt][nt][0]);
                acc[mt][nt][1] = fmaf(kv0, T[mt][nt][1], acc[mt][nt][1]);
                acc[mt][nt][2] = fmaf(kv1, T[mt][nt][2], acc[mt][nt][2]);
                acc[mt][nt][3] = fmaf(kv1, T[mt][nt][3], acc[mt][nt][3]);
            }
        }
    }

    // epilogue: bias + relu, direct stores (8-pixel groups -> full 32B sectors)
#pragma unroll
    for (int mt = 0; mt < 2; mt++) {
        int pix = warpM * 32 + mt * 16 + (lane >> 2);
#pragma unroll
        for (int nt = 0; nt < 2; nt++) {
            int o = warpN * 16 + nt * 8 + (lane & 3) * 2;
            float b0 = bias_s[o], b1 = bias_s[o + 1];
            float* op = out + (((size_t)b * COUT + o) * HH + h) * WW;
            op[pix]                = fmaxf(acc[mt][nt][0] + b0, 0.f);
            op[HH * WW + pix]      = fmaxf(acc[mt][nt][1] + b1, 0.f);
            op[pix + 8]            = fmaxf(acc[mt][nt][2] + b0, 0.f);
            op[HH * WW + pix + 8]  = fmaxf(acc[mt][nt][3] + b1, 0.f);
        }
    }
}

// ---------------------------------------------------------------------------
extern "C" void kernel_launch(void* const* d_in, const int* in_sizes, int n_in,
                              void* d_out, int out_size) {
    const float* x      = (const float*)d_in[0];   // (8,64,128,128)
    const float* guide  = (const float*)d_in[1];   // (8,16,128,128)
    const float* weight = (const float*)d_in[2];   // (64,64,3,3)
    const float* bias   = (const float*)d_in[3];   // (64,)
    float* out = (float*)d_out;                    // (8,64,128,128)

    (void)in_sizes; (void)n_in; (void)out_size;

    cudaFuncSetAttribute(pac_mma, cudaFuncAttributeMaxDynamicSharedMemorySize,
                         SMEM_TOTAL);

    int npix = BB * HH * WW;
    kern_precompute<<<(npix + 255) / 256, 256>>>(guide);
    weight_split<<<(9 * 2 * 2048 + 255) / 256, 256>>>(weight);

    dim3 grid(HH, BB);
    pac_mma<<<grid, 512, SMEM_TOTAL>>>(x, bias, out);
}